// round 12
// baseline (speedup 1.0000x reference)
#include <cuda_runtime.h>
#include <cuda_bf16.h>
#include <cstdint>

// Problem constants (GCNEncoder_55052890800619)
#define NN 100000
#define DD 128
#define HH 256
#define EE 1600000

// ---------------- scratch (device globals; no allocations allowed) ----------
__device__ int   g_cnt[NN];
__device__ int   g_rowptr[NN];
__device__ int   g_cursor[NN];
__device__ float g_dinv[NN];
__device__ int   g_chain[128];               // scan aggregates (value+1; 0 = unpublished)
__device__ __align__(16) int2  g_csr[EE];                  // 12.8 MB
__device__ __align__(16) float g_aggemb[(size_t)NN * DD];  // 51.2 MB  agg(emb)
__device__ __align__(16) float g_xw2   [(size_t)NN * DD];  // 51.2 MB

// ---------------- per-block edge dtype detection -----------------------------
__device__ __forceinline__ int block_detect_is64(const unsigned int* __restrict__ p,
                                                 int* s_is64) {
    if (threadIdx.x < 32) {
        int any = 0;
        #pragma unroll
        for (int q = 0; q < 2; q++) {
            long long j = (long long)(threadIdx.x * 2 + q) * 24999 + 7;  // < 1.6M
            any |= (p[2 * j + 1] != 0u);
        }
        any = __any_sync(0xffffffffu, any);
        if (threadIdx.x == 0) *s_is64 = any ? 0 : 1;
    }
    __syncthreads();
    return *s_is64;
}

__device__ __forceinline__ int2 load_edge(const void* eptr, int E, int e, int is64) {
    int2 r;
    if (is64) {
        const long long* q = (const long long*)eptr;
        r.x = (int)q[e];
        r.y = (int)q[(size_t)E + e];
    } else {
        const int* q = (const int*)eptr;
        r.x = q[e];
        r.y = q[(size_t)E + e];
    }
    return r;
}

// ---------------- prep kernels (3 launches) ----------------------------------
__global__ void count_kernel(const unsigned int* __restrict__ eptr, int E) {
    __shared__ int s_is64;
    int is64 = block_detect_is64(eptr, &s_is64);
    if (blockIdx.x == 0 && threadIdx.x < 128) g_chain[threadIdx.x] = 0;
    int e = blockIdx.x * blockDim.x + threadIdx.x;
    if (e >= E) return;
    int d;
    if (is64) d = (int)(((const long long*)eptr)[(size_t)E + e]);
    else      d = ((const int*)eptr)[(size_t)E + e];
    atomicAdd(&g_cnt[d], 1);
}

__global__ void scan_fused_kernel(int n) {
    __shared__ int sh[1024];
    __shared__ int agg[128];
    __shared__ int s_prefix;
    const int b   = blockIdx.x;
    const int tid = threadIdx.x;
    const int gid = b * 1024 + tid;

    int v = (gid < n) ? g_cnt[gid] : 0;
    if (gid < n) g_dinv[gid] = rsqrtf((float)v + 1.0f);
    sh[tid] = v;
    __syncthreads();
    for (int off = 1; off < 1024; off <<= 1) {
        int t = (tid >= (unsigned)off) ? sh[tid - off] : 0;
        __syncthreads();
        sh[tid] += t;
        __syncthreads();
    }
    if (tid == 0) atomicExch(&g_chain[b], sh[1023] + 1);
    if (tid < 128) agg[tid] = 0;
    if (tid < b) {
        int p;
        do { p = atomicAdd(&g_chain[tid], 0); } while (p == 0);
        agg[tid] = p - 1;
    }
    __syncthreads();
    if (tid == 0) {
        int s = 0;
        #pragma unroll 4
        for (int i = 0; i < b; i++) s += agg[i];
        s_prefix = s;
    }
    __syncthreads();
    if (gid < n) {
        int r = s_prefix + sh[tid] - v;
        g_rowptr[gid] = r;
        g_cursor[gid] = r;
    }
}

__global__ void csr_fill_kernel(const unsigned int* __restrict__ eptr, int E) {
    __shared__ int s_is64;
    int is64 = block_detect_is64(eptr, &s_is64);
    int e = blockIdx.x * blockDim.x + threadIdx.x;
    if (e >= E) return;
    int2 sd = load_edge(eptr, E, e, is64);
    int pos = atomicAdd(&g_cursor[sd.y], 1);
    float w = g_dinv[sd.x] * g_dinv[sd.y];
    g_csr[pos] = make_int2(sd.x, __float_as_int(w));
}

// ---------------- bf16 split helpers ----------------------------------------
__device__ __forceinline__ void split_pack(float x0, float x1,
                                           uint32_t& hi, uint32_t& lo) {
    uint32_t h;
    asm("cvt.rn.bf16x2.f32 %0, %1, %2;" : "=r"(h) : "f"(x1), "f"(x0));
    float e0 = x0 - __uint_as_float(h << 16);
    float e1 = x1 - __uint_as_float(h & 0xffff0000u);
    asm("cvt.rn.bf16x2.f32 %0, %1, %2;" : "=r"(lo) : "f"(e1), "f"(e0));
    hi = h;
}

__device__ __forceinline__ void mma16(float* c, const uint32_t* a, const uint32_t* b) {
    asm volatile(
        "mma.sync.aligned.m16n8k16.row.col.f32.bf16.bf16.f32 "
        "{%0,%1,%2,%3}, {%4,%5,%6,%7}, {%8,%9}, {%0,%1,%2,%3};"
        : "+f"(c[0]), "+f"(c[1]), "+f"(c[2]), "+f"(c[3])
        : "r"(a[0]), "r"(a[1]), "r"(a[2]), "r"(a[3]), "r"(b[0]), "r"(b[1]));
}

// kpair (0..7) -> smem column (pairs (t, t+4) adjacent -> one LDS.64/frag)
__device__ __forceinline__ int colmap(int kp) {
    return ((kp & 3) << 1) | ((kp >> 2) & 1);
}

// ---------------- FUSED GEMM: xw2 = relu(aggemb@W1 + b1) @ W2 ----------------
// One CTA = 128 rows. Phase A: compute x (two 128-col halves) into smem X
// buffers (bf16 hi/lo, stage-2 fragment layout). Phase B: acc2 = X @ W2.
// 256 threads = 8 warps, warp tile 64x32, 1 CTA/SM (204.8 KB dynamic smem).
__global__ void __launch_bounds__(256, 1)
fused_gemm(const float* __restrict__ A, const float* __restrict__ W1,
           const float* __restrict__ b1, const float* __restrict__ W2,
           float* __restrict__ C, int M)
{
    extern __shared__ uint32_t smbuf[];
    // tile buffers: [2][128][10] each
    uint32_t (*Ahi)[10] = (uint32_t(*)[10])smbuf;          // rows 0..255
    uint32_t (*Alo)[10] = Ahi + 256;
    uint32_t (*Bhi)[10] = Alo + 256;
    uint32_t (*Blo)[10] = Bhi + 256;
    // X buffers: [16][128][10] each (bf16x2 hi/lo, fragment layout)
    uint32_t (*Xhi)[10] = Blo + 256;                       // rows 0..2047
    uint32_t (*Xlo)[10] = Xhi + 2048;

    const int tid  = threadIdx.x;
    const int wid  = tid >> 5;
    const int lane = tid & 31;
    const int g    = lane >> 2;
    const int t    = lane & 3;
    const int brow = blockIdx.x * 128;
    const int wm   = (wid >> 2) * 64;   // 0 or 64
    const int wn   = (wid & 3) * 32;    // 0,32,64,96

    const int am0  = tid >> 2;          // A loader row (0..63), +64 for second
    const int akq0 = tid & 3;           // A float4-k
    const int bkp  = tid >> 5;          // B kpair 0..7
    const int bn4  = tid & 31;          // B float4-n

    float4 va0, va1, vb0, vb1;

    // ================= Phase A: x halves -> X smem =================
    for (int h = 0; h < 2; h++) {
        float acc1[4][4][4];
        #pragma unroll
        for (int mt = 0; mt < 4; mt++)
            #pragma unroll
            for (int nt = 0; nt < 4; nt++)
                #pragma unroll
                for (int i = 0; i < 4; i++) acc1[mt][nt][i] = 0.0f;

        auto fetch1 = [&](int grp) {
            int k0 = grp * 16;
            int r0 = brow + am0;
            int r1 = brow + am0 + 64;
            va0 = make_float4(0.f, 0.f, 0.f, 0.f);
            va1 = make_float4(0.f, 0.f, 0.f, 0.f);
            if (r0 < M) va0 = *(const float4*)(A + (size_t)r0 * DD + k0 + akq0 * 4);
            if (r1 < M) va1 = *(const float4*)(A + (size_t)r1 * DD + k0 + akq0 * 4);
            const float* br = W1 + (size_t)(k0 + 2 * bkp) * HH + h * 128 + bn4 * 4;
            vb0 = *(const float4*)br;
            vb1 = *(const float4*)(br + HH);
        };
        auto stage1 = [&](int buf) {
            uint32_t h0, l0, h1, l1;
            split_pack(va0.x, va0.y, h0, l0);
            split_pack(va0.z, va0.w, h1, l1);
            int c0 = colmap(2 * akq0), c1 = colmap(2 * akq0 + 1);
            int rb = buf * 128 + am0;
            Ahi[rb][c0] = h0; Alo[rb][c0] = l0;
            Ahi[rb][c1] = h1; Alo[rb][c1] = l1;
            split_pack(va1.x, va1.y, h0, l0);
            split_pack(va1.z, va1.w, h1, l1);
            Ahi[rb + 64][c0] = h0; Alo[rb + 64][c0] = l0;
            Ahi[rb + 64][c1] = h1; Alo[rb + 64][c1] = l1;
            int cb = colmap(bkp);
            int nb = buf * 128 + bn4 * 4;
            uint32_t hh, ll;
            split_pack(vb0.x, vb1.x, hh, ll); Bhi[nb + 0][cb] = hh; Blo[nb + 0][cb] = ll;
            split_pack(vb0.y, vb1.y, hh, ll); Bhi[nb + 1][cb] = hh; Blo[nb + 1][cb] = ll;
            split_pack(vb0.z, vb1.z, hh, ll); Bhi[nb + 2][cb] = hh; Blo[nb + 2][cb] = ll;
            split_pack(vb0.w, vb1.w, hh, ll); Bhi[nb + 3][cb] = hh; Blo[nb + 3][cb] = ll;
        };

        fetch1(0);
        stage1(0);
        __syncthreads();

        for (int grp = 0; grp < 8; grp++) {
            int cur = grp & 1;
            if (grp + 1 < 8) fetch1(grp + 1);
            {
                const int cb = 2 * t;
                uint32_t ah[4][4], al[4][4];
                #pragma unroll
                for (int mt = 0; mt < 4; mt++) {
                    int r = cur * 128 + wm + mt * 16;
                    uint2 p0 = *(const uint2*)&Ahi[r + g    ][cb];
                    uint2 p1 = *(const uint2*)&Ahi[r + g + 8][cb];
                    ah[mt][0] = p0.x; ah[mt][2] = p0.y;
                    ah[mt][1] = p1.x; ah[mt][3] = p1.y;
                    uint2 q0 = *(const uint2*)&Alo[r + g    ][cb];
                    uint2 q1 = *(const uint2*)&Alo[r + g + 8][cb];
                    al[mt][0] = q0.x; al[mt][2] = q0.y;
                    al[mt][1] = q1.x; al[mt][3] = q1.y;
                }
                #pragma unroll
                for (int nt = 0; nt < 4; nt++) {
                    uint2 bh2 = *(const uint2*)&Bhi[cur * 128 + wn + nt * 8 + g][cb];
                    uint2 bl2 = *(const uint2*)&Blo[cur * 128 + wn + nt * 8 + g][cb];
                    uint32_t bh[2] = {bh2.x, bh2.y};
                    uint32_t bl[2] = {bl2.x, bl2.y};
                    #pragma unroll
                    for (int mt = 0; mt < 4; mt++) {
                        mma16(acc1[mt][nt], ah[mt], bh);
                        mma16(acc1[mt][nt], ah[mt], bl);
                        mma16(acc1[mt][nt], al[mt], bh);
                    }
                }
            }
            if (grp + 1 < 8) stage1(cur ^ 1);
            __syncthreads();
        }

        // bias + relu + split -> X buffers (stage-2 A-fragment layout)
        #pragma unroll
        for (int nt = 0; nt < 4; nt++) {
            int col = wn + nt * 8 + 2 * t;
            int gc  = h * 128 + col;
            float bb0 = b1[gc], bb1 = b1[gc + 1];
            int xr = (gc >> 4) * 128;
            int c  = colmap((gc >> 1) & 7);
            #pragma unroll
            for (int mt = 0; mt < 4; mt++) {
                int r0 = wm + mt * 16 + g;
                uint32_t hh, ll;
                split_pack(fmaxf(acc1[mt][nt][0] + bb0, 0.f),
                           fmaxf(acc1[mt][nt][1] + bb1, 0.f), hh, ll);
                Xhi[xr + r0][c] = hh; Xlo[xr + r0][c] = ll;
                split_pack(fmaxf(acc1[mt][nt][2] + bb0, 0.f),
                           fmaxf(acc1[mt][nt][3] + bb1, 0.f), hh, ll);
                Xhi[xr + r0 + 8][c] = hh; Xlo[xr + r0 + 8][c] = ll;
            }
        }
    }

    // ================= Phase B: acc2 = X @ W2 =================
    float acc2[4][4][4];
    #pragma unroll
    for (int mt = 0; mt < 4; mt++)
        #pragma unroll
        for (int nt = 0; nt < 4; nt++)
            #pragma unroll
            for (int i = 0; i < 4; i++) acc2[mt][nt][i] = 0.0f;

    auto fetchB = [&](int grp) {
        const float* br = W2 + (size_t)(grp * 16 + 2 * bkp) * DD + bn4 * 4;
        vb0 = *(const float4*)br;
        vb1 = *(const float4*)(br + DD);
    };
    auto stageB = [&](int buf) {
        int cb = colmap(bkp);
        int nb = buf * 128 + bn4 * 4;
        uint32_t hh, ll;
        split_pack(vb0.x, vb1.x, hh, ll); Bhi[nb + 0][cb] = hh; Blo[nb + 0][cb] = ll;
        split_pack(vb0.y, vb1.y, hh, ll); Bhi[nb + 1][cb] = hh; Blo[nb + 1][cb] = ll;
        split_pack(vb0.z, vb1.z, hh, ll); Bhi[nb + 2][cb] = hh; Blo[nb + 2][cb] = ll;
        split_pack(vb0.w, vb1.w, hh, ll); Bhi[nb + 3][cb] = hh; Blo[nb + 3][cb] = ll;
    };

    fetchB(0);
    stageB(0);
    __syncthreads();   // also publishes all X writes

    for (int grp = 0; grp < 16; grp++) {
        int cur = grp & 1;
        if (grp + 1 < 16) fetchB(grp + 1);
        {
            const int cb = 2 * t;
            uint32_t ah[4][4], al[4][4];
            #pragma unroll
            for (int mt = 0; mt < 4; mt++) {
                int r = grp * 128 + wm + mt * 16;
                uint2 p0 = *(const uint2*)&Xhi[r + g    ][cb];
                uint2 p1 = *(const uint2*)&Xhi[r + g + 8][cb];
                ah[mt][0] = p0.x; ah[mt][2] = p0.y;
                ah[mt][1] = p1.x; ah[mt][3] = p1.y;
                uint2 q0 = *(const uint2*)&Xlo[r + g    ][cb];
                uint2 q1 = *(const uint2*)&Xlo[r + g + 8][cb];
                al[mt][0] = q0.x; al[mt][2] = q0.y;
                al[mt][1] = q1.x; al[mt][3] = q1.y;
            }
            #pragma unroll
            for (int nt = 0; nt < 4; nt++) {
                uint2 bh2 = *(const uint2*)&Bhi[cur * 128 + wn + nt * 8 + g][cb];
                uint2 bl2 = *(const uint2*)&Blo[cur * 128 + wn + nt * 8 + g][cb];
                uint32_t bh[2] = {bh2.x, bh2.y};
                uint32_t bl[2] = {bl2.x, bl2.y};
                #pragma unroll
                for (int mt = 0; mt < 4; mt++) {
                    mma16(acc2[mt][nt], ah[mt], bh);
                    mma16(acc2[mt][nt], ah[mt], bl);
                    mma16(acc2[mt][nt], al[mt], bh);
                }
            }
        }
        if (grp + 1 < 16) stageB(cur ^ 1);
        __syncthreads();
    }

    // epilogue: write xw2 (no bias; agg2 adds b2)
    #pragma unroll
    for (int nt = 0; nt < 4; nt++) {
        int col = wn + nt * 8 + 2 * t;
        #pragma unroll
        for (int mt = 0; mt < 4; mt++) {
            int r0 = brow + wm + mt * 16 + g;
            if (r0 < M)
                *(float2*)(C + (size_t)r0 * DD + col) =
                    make_float2(acc2[mt][nt][0], acc2[mt][nt][1]);
            if (r0 + 8 < M)
                *(float2*)(C + (size_t)(r0 + 8) * DD + col) =
                    make_float2(acc2[mt][nt][2], acc2[mt][nt][3]);
        }
    }
}

// ---------------- aggregation (128 cols): warp per node, MLP=8 --------------
template <bool ADD_BIAS>
__global__ void __launch_bounds__(256)
agg128(const float* __restrict__ xw, const float* __restrict__ bias,
       float* __restrict__ out, int n)
{
    int node = (blockIdx.x * 256 + threadIdx.x) >> 5;
    int lane = threadIdx.x & 31;
    if (node >= n) return;

    float dsq = g_dinv[node];
    dsq *= dsq;
    const float4* base = (const float4*)xw;
    float4 tv = base[(size_t)node * 32 + lane];
    float4 acc = make_float4(tv.x * dsq, tv.y * dsq, tv.z * dsq, tv.w * dsq);

    int j   = g_rowptr[node];
    int end = j + g_cnt[node];

    for (; j + 8 <= end; j += 8) {
        int2 e[8];
        #pragma unroll
        for (int q = 0; q < 8; q++) e[q] = g_csr[j + q];
        float4 p[8];
        #pragma unroll
        for (int q = 0; q < 8; q++) p[q] = base[(size_t)e[q].x * 32 + lane];
        #pragma unroll
        for (int q = 0; q < 8; q++) {
            float w = __int_as_float(e[q].y);
            acc.x = fmaf(p[q].x, w, acc.x); acc.y = fmaf(p[q].y, w, acc.y);
            acc.z = fmaf(p[q].z, w, acc.z); acc.w = fmaf(p[q].w, w, acc.w);
        }
    }
    if (j + 4 <= end) {
        int2 e[4];
        #pragma unroll
        for (int q = 0; q < 4; q++) e[q] = g_csr[j + q];
        float4 p[4];
        #pragma unroll
        for (int q = 0; q < 4; q++) p[q] = base[(size_t)e[q].x * 32 + lane];
        #pragma unroll
        for (int q = 0; q < 4; q++) {
            float w = __int_as_float(e[q].y);
            acc.x = fmaf(p[q].x, w, acc.x); acc.y = fmaf(p[q].y, w, acc.y);
            acc.z = fmaf(p[q].z, w, acc.z); acc.w = fmaf(p[q].w, w, acc.w);
        }
        j += 4;
    }
    for (; j < end; j++) {
        int2 e = g_csr[j];
        float w = __int_as_float(e.y);
        float4 p = base[(size_t)e.x * 32 + lane];
        acc.x = fmaf(p.x, w, acc.x); acc.y = fmaf(p.y, w, acc.y);
        acc.z = fmaf(p.z, w, acc.z); acc.w = fmaf(p.w, w, acc.w);
    }

    if (ADD_BIAS) {
        float4 b = *((const float4*)bias + lane);
        acc.x += b.x; acc.y += b.y; acc.z += b.z; acc.w += b.w;
    }
    *((float4*)out + (size_t)node * 32 + lane) = acc;
}

// ---------------- launch -----------------------------------------------------
extern "C" void kernel_launch(void* const* d_in, const int* in_sizes, int n_in,
                              void* d_out, int out_size)
{
    const float* emb = (const float*)d_in[0];   // [N, D]
    const float* W1  = (const float*)d_in[1];   // [D, H]
    const float* b1  = (const float*)d_in[2];   // [H]
    const float* W2  = (const float*)d_in[3];   // [H, D]
    const float* b2  = (const float*)d_in[4];   // [D]
    const void*  eix = d_in[5];                 // [2, E] int64 or int32
    float* out = (float*)d_out;                 // [N, D]

    const int D = in_sizes[4];          // 128
    const int H = in_sizes[2];          // 256
    const int N = in_sizes[0] / D;      // 100000
    const int E = in_sizes[5] / 2;      // 1600000
    const int NB = (N + 1023) / 1024;   // 98 scan blocks (co-resident)
    (void)D; (void)H;

    float *p_aggemb, *p_xw2;
    int* p_cnt;
    cudaGetSymbolAddress((void**)&p_aggemb, g_aggemb);
    cudaGetSymbolAddress((void**)&p_xw2,    g_xw2);
    cudaGetSymbolAddress((void**)&p_cnt,    g_cnt);

    constexpr int FUSED_SMEM = (4 * 2 * 128 * 10 + 2 * 16 * 128 * 10) * 4;  // 204800
    cudaFuncSetAttribute(fused_gemm,
                         cudaFuncAttributeMaxDynamicSharedMemorySize, FUSED_SMEM);

    // ---- graph prep: memset + 3 kernels ----
    cudaMemsetAsync(p_cnt, 0, (size_t)N * sizeof(int));
    count_kernel<<<(E + 255) / 256, 256>>>((const unsigned int*)eix, E);
    scan_fused_kernel<<<NB, 1024>>>(N);
    csr_fill_kernel<<<(E + 255) / 256, 256>>>((const unsigned int*)eix, E);

    // ---- layer 1 agg, then fused GEMM chain, then layer 2 agg ----
    agg128<false><<<(N + 7) / 8, 256>>>(emb, nullptr, p_aggemb, N);
    fused_gemm<<<(N + 127) / 128, 256, FUSED_SMEM>>>(p_aggemb, W1, b1, W2, p_xw2, N);
    agg128<true><<<(N + 7) / 8, 256>>>(p_xw2, b2, out, N);
}

// round 15
// speedup vs baseline: 1.1786x; 1.1786x over previous
#include <cuda_runtime.h>
#include <cuda_bf16.h>
#include <cuda_fp16.h>
#include <cstdint>

// Problem constants (GCNEncoder_55052890800619)
#define NN 100000
#define DD 128
#define HH 256
#define EE 1600000

// ---------------- scratch (device globals; no allocations allowed) ----------
__device__ int   g_cnt[NN];
__device__ int   g_rowptr[NN];
__device__ int   g_cursor[NN];
__device__ float g_dinv[NN];
__device__ int   g_chain[128];               // scan aggregates (value+1; 0 = unpublished)
__device__ __align__(16) int2  g_csr[EE];                  // 12.8 MB
__device__ __align__(16) float g_aggemb[(size_t)NN * DD];  // 51.2 MB  agg(emb)
__device__ __align__(16) float g_x     [(size_t)NN * HH];  // 102.4 MB
__device__ __align__(16) float g_xw2   [(size_t)NN * DD];  // 51.2 MB

// ---------------- per-block edge dtype detection -----------------------------
__device__ __forceinline__ int block_detect_is64(const unsigned int* __restrict__ p,
                                                 int* s_is64) {
    if (threadIdx.x < 32) {
        int any = 0;
        #pragma unroll
        for (int q = 0; q < 2; q++) {
            long long j = (long long)(threadIdx.x * 2 + q) * 24999 + 7;  // < 1.6M
            any |= (p[2 * j + 1] != 0u);
        }
        any = __any_sync(0xffffffffu, any);
        if (threadIdx.x == 0) *s_is64 = any ? 0 : 1;
    }
    __syncthreads();
    return *s_is64;
}

__device__ __forceinline__ int2 load_edge(const void* eptr, int E, int e, int is64) {
    int2 r;
    if (is64) {
        const long long* q = (const long long*)eptr;
        r.x = (int)q[e];
        r.y = (int)q[(size_t)E + e];
    } else {
        const int* q = (const int*)eptr;
        r.x = q[e];
        r.y = q[(size_t)E + e];
    }
    return r;
}

// ---------------- prep kernels (3 launches) ----------------------------------
__global__ void count_kernel(const unsigned int* __restrict__ eptr, int E) {
    __shared__ int s_is64;
    int is64 = block_detect_is64(eptr, &s_is64);
    if (blockIdx.x == 0 && threadIdx.x < 128) g_chain[threadIdx.x] = 0;
    int e = blockIdx.x * blockDim.x + threadIdx.x;
    if (e >= E) return;
    int d;
    if (is64) d = (int)(((const long long*)eptr)[(size_t)E + e]);
    else      d = ((const int*)eptr)[(size_t)E + e];
    atomicAdd(&g_cnt[d], 1);
}

__global__ void scan_fused_kernel(int n) {
    __shared__ int sh[1024];
    __shared__ int agg[128];
    __shared__ int s_prefix;
    const int b   = blockIdx.x;
    const int tid = threadIdx.x;
    const int gid = b * 1024 + tid;

    int v = (gid < n) ? g_cnt[gid] : 0;
    if (gid < n) g_dinv[gid] = rsqrtf((float)v + 1.0f);
    sh[tid] = v;
    __syncthreads();
    for (int off = 1; off < 1024; off <<= 1) {
        int t = (tid >= (unsigned)off) ? sh[tid - off] : 0;
        __syncthreads();
        sh[tid] += t;
        __syncthreads();
    }
    if (tid == 0) atomicExch(&g_chain[b], sh[1023] + 1);
    if (tid < 128) agg[tid] = 0;
    if (tid < b) {
        int p;
        do { p = atomicAdd(&g_chain[tid], 0); } while (p == 0);
        agg[tid] = p - 1;
    }
    __syncthreads();
    if (tid == 0) {
        int s = 0;
        #pragma unroll 4
        for (int i = 0; i < b; i++) s += agg[i];
        s_prefix = s;
    }
    __syncthreads();
    if (gid < n) {
        int r = s_prefix + sh[tid] - v;
        g_rowptr[gid] = r;
        g_cursor[gid] = r;
    }
}

__global__ void csr_fill_kernel(const unsigned int* __restrict__ eptr, int E) {
    __shared__ int s_is64;
    int is64 = block_detect_is64(eptr, &s_is64);
    int e = blockIdx.x * blockDim.x + threadIdx.x;
    if (e >= E) return;
    int2 sd = load_edge(eptr, E, e, is64);
    int pos = atomicAdd(&g_cursor[sd.y], 1);
    float w = g_dinv[sd.x] * g_dinv[sd.y];
    g_csr[pos] = make_int2(sd.x, __float_as_int(w));
}

// ---------------- fp16 helpers ----------------------------------------------
__device__ __forceinline__ uint32_t pack_f16(float x0, float x1) {
    uint32_t h;
    asm("cvt.rn.f16x2.f32 %0, %1, %2;" : "=r"(h) : "f"(x1), "f"(x0));
    return h;   // low half = x0, high half = x1
}

// A split: hi captures fp16(x), lo captures residual (A effectively exact)
__device__ __forceinline__ void split_pack_f16(float x0, float x1,
                                               uint32_t& hi, uint32_t& lo) {
    uint32_t h = pack_f16(x0, x1);
    __half2 hh = *reinterpret_cast<__half2*>(&h);
    float2 f = __half22float2(hh);
    lo = pack_f16(x0 - f.x, x1 - f.y);
    hi = h;
}

__device__ __forceinline__ void mma16f(float* c, const uint32_t* a, const uint32_t* b) {
    asm volatile(
        "mma.sync.aligned.m16n8k16.row.col.f32.f16.f16.f32 "
        "{%0,%1,%2,%3}, {%4,%5,%6,%7}, {%8,%9}, {%0,%1,%2,%3};"
        : "+f"(c[0]), "+f"(c[1]), "+f"(c[2]), "+f"(c[3])
        : "r"(a[0]), "r"(a[1]), "r"(a[2]), "r"(a[3]), "r"(b[0]), "r"(b[1]));
}

// kpair (0..7) -> smem column (pairs (t, t+4) adjacent -> one LDS.64/frag)
__device__ __forceinline__ int colmap(int kp) {
    return ((kp & 3) << 1) | ((kp >> 2) & 1);
}

// ---------------- GEMM: fp16 2-term (A hi+lo, B hi), pipelined ---------------
// Block 128x128, BK=16, 256 threads = 8 warps, warp tile 64x32, 2 CTAs/SM.
#define GSTR 10

template <bool RELU_BIAS>
__global__ void __launch_bounds__(256, 2)
gemm_f16(const float* __restrict__ A, const float* __restrict__ B,
         const float* __restrict__ bias, float* __restrict__ C,
         int M, int N, int K)
{
    __shared__ uint32_t Ahi[2][128][GSTR], Alo[2][128][GSTR];
    __shared__ uint32_t Bhs[2][128][GSTR];

    const int tid  = threadIdx.x;
    const int wid  = tid >> 5;
    const int lane = tid & 31;
    const int g    = lane >> 2;
    const int t    = lane & 3;
    const int brow = blockIdx.y * 128;
    const int bcol = blockIdx.x * 128;
    const int wm   = (wid >> 2) * 64;   // 0 or 64
    const int wn   = (wid & 3) * 32;    // 0,32,64,96

    const int am0  = tid >> 2;          // A row for q=0 (0..63)
    const int akq0 = tid & 3;           // A float4-k
    const int bkp  = tid >> 5;          // B kpair 0..7
    const int bn4  = tid & 31;          // B float4-n

    const int ngrp = K >> 4;

    float acc[4][4][4];
    #pragma unroll
    for (int mt = 0; mt < 4; mt++)
        #pragma unroll
        for (int nt = 0; nt < 4; nt++)
            #pragma unroll
            for (int i = 0; i < 4; i++) acc[mt][nt][i] = 0.0f;

    float4 va0, va1, vb0, vb1;

    auto fetch = [&](int grp) {
        int k0 = grp * 16;
        int r0 = brow + am0;
        int r1 = brow + am0 + 64;
        va0 = make_float4(0.f, 0.f, 0.f, 0.f);
        va1 = make_float4(0.f, 0.f, 0.f, 0.f);
        if (r0 < M) va0 = *(const float4*)(A + (size_t)r0 * K + k0 + akq0 * 4);
        if (r1 < M) va1 = *(const float4*)(A + (size_t)r1 * K + k0 + akq0 * 4);
        const float* br = B + (size_t)(k0 + 2 * bkp) * N + bcol + bn4 * 4;
        vb0 = *(const float4*)br;
        vb1 = *(const float4*)(br + N);
    };
    auto stage = [&](int buf) {
        uint32_t h0, l0, h1, l1;
        split_pack_f16(va0.x, va0.y, h0, l0);
        split_pack_f16(va0.z, va0.w, h1, l1);
        int c0 = colmap(2 * akq0), c1 = colmap(2 * akq0 + 1);
        Ahi[buf][am0][c0] = h0; Alo[buf][am0][c0] = l0;
        Ahi[buf][am0][c1] = h1; Alo[buf][am0][c1] = l1;
        split_pack_f16(va1.x, va1.y, h0, l0);
        split_pack_f16(va1.z, va1.w, h1, l1);
        Ahi[buf][am0 + 64][c0] = h0; Alo[buf][am0 + 64][c0] = l0;
        Ahi[buf][am0 + 64][c1] = h1; Alo[buf][am0 + 64][c1] = l1;
        int cb = colmap(bkp);
        Bhs[buf][bn4 * 4 + 0][cb] = pack_f16(vb0.x, vb1.x);
        Bhs[buf][bn4 * 4 + 1][cb] = pack_f16(vb0.y, vb1.y);
        Bhs[buf][bn4 * 4 + 2][cb] = pack_f16(vb0.z, vb1.z);
        Bhs[buf][bn4 * 4 + 3][cb] = pack_f16(vb0.w, vb1.w);
    };

    fetch(0);
    stage(0);
    __syncthreads();

    for (int grp = 0; grp < ngrp; grp++) {
        int cur = grp & 1;
        if (grp + 1 < ngrp) fetch(grp + 1);

        {
            const int cb = 2 * t;
            uint32_t ah[4][4], al[4][4];
            #pragma unroll
            for (int mt = 0; mt < 4; mt++) {
                int r = wm + mt * 16;
                uint2 p0 = *(const uint2*)&Ahi[cur][r + g    ][cb];
                uint2 p1 = *(const uint2*)&Ahi[cur][r + g + 8][cb];
                ah[mt][0] = p0.x; ah[mt][2] = p0.y;
                ah[mt][1] = p1.x; ah[mt][3] = p1.y;
                uint2 q0 = *(const uint2*)&Alo[cur][r + g    ][cb];
                uint2 q1 = *(const uint2*)&Alo[cur][r + g + 8][cb];
                al[mt][0] = q0.x; al[mt][2] = q0.y;
                al[mt][1] = q1.x; al[mt][3] = q1.y;
            }
            #pragma unroll
            for (int nt = 0; nt < 4; nt++) {
                uint2 bh2 = *(const uint2*)&Bhs[cur][wn + nt * 8 + g][cb];
                uint32_t bh[2] = {bh2.x, bh2.y};
                #pragma unroll
                for (int mt = 0; mt < 4; mt++) {
                    mma16f(acc[mt][nt], ah[mt], bh);
                    mma16f(acc[mt][nt], al[mt], bh);
                }
            }
        }

        if (grp + 1 < ngrp) stage(cur ^ 1);
        __syncthreads();
    }

    #pragma unroll
    for (int nt = 0; nt < 4; nt++) {
        int col = bcol + wn + nt * 8 + 2 * t;
        float b0 = 0.f, b1 = 0.f;
        if (RELU_BIAS) { b0 = bias[col]; b1 = bias[col + 1]; }
        #pragma unroll
        for (int mt = 0; mt < 4; mt++) {
            int r0 = brow + wm + mt * 16 + g;
            float2 v0 = make_float2(acc[mt][nt][0] + b0, acc[mt][nt][1] + b1);
            float2 v1 = make_float2(acc[mt][nt][2] + b0, acc[mt][nt][3] + b1);
            if (RELU_BIAS) {
                v0.x = fmaxf(v0.x, 0.f); v0.y = fmaxf(v0.y, 0.f);
                v1.x = fmaxf(v1.x, 0.f); v1.y = fmaxf(v1.y, 0.f);
            }
            if (r0 < M)     *(float2*)(C + (size_t)r0 * N + col) = v0;
            if (r0 + 8 < M) *(float2*)(C + (size_t)(r0 + 8) * N + col) = v1;
        }
    }
}

// ---------------- aggregation (128 cols): warp per node, MLP=8 --------------
template <bool ADD_BIAS>
__global__ void __launch_bounds__(256)
agg128(const float* __restrict__ xw, const float* __restrict__ bias,
       float* __restrict__ out, int n)
{
    int node = (blockIdx.x * 256 + threadIdx.x) >> 5;
    int lane = threadIdx.x & 31;
    if (node >= n) return;

    float dsq = g_dinv[node];
    dsq *= dsq;
    const float4* base = (const float4*)xw;
    float4 tv = base[(size_t)node * 32 + lane];
    float4 acc = make_float4(tv.x * dsq, tv.y * dsq, tv.z * dsq, tv.w * dsq);

    int j   = g_rowptr[node];
    int end = j + g_cnt[node];

    for (; j + 8 <= end; j += 8) {
        int2 e[8];
        #pragma unroll
        for (int q = 0; q < 8; q++) e[q] = g_csr[j + q];
        float4 p[8];
        #pragma unroll
        for (int q = 0; q < 8; q++) p[q] = base[(size_t)e[q].x * 32 + lane];
        #pragma unroll
        for (int q = 0; q < 8; q++) {
            float w = __int_as_float(e[q].y);
            acc.x = fmaf(p[q].x, w, acc.x); acc.y = fmaf(p[q].y, w, acc.y);
            acc.z = fmaf(p[q].z, w, acc.z); acc.w = fmaf(p[q].w, w, acc.w);
        }
    }
    if (j + 4 <= end) {
        int2 e[4];
        #pragma unroll
        for (int q = 0; q < 4; q++) e[q] = g_csr[j + q];
        float4 p[4];
        #pragma unroll
        for (int q = 0; q < 4; q++) p[q] = base[(size_t)e[q].x * 32 + lane];
        #pragma unroll
        for (int q = 0; q < 4; q++) {
            float w = __int_as_float(e[q].y);
            acc.x = fmaf(p[q].x, w, acc.x); acc.y = fmaf(p[q].y, w, acc.y);
            acc.z = fmaf(p[q].z, w, acc.z); acc.w = fmaf(p[q].w, w, acc.w);
        }
        j += 4;
    }
    for (; j < end; j++) {
        int2 e = g_csr[j];
        float w = __int_as_float(e.y);
        float4 p = base[(size_t)e.x * 32 + lane];
        acc.x = fmaf(p.x, w, acc.x); acc.y = fmaf(p.y, w, acc.y);
        acc.z = fmaf(p.z, w, acc.z); acc.w = fmaf(p.w, w, acc.w);
    }

    if (ADD_BIAS) {
        float4 b = *((const float4*)bias + lane);
        acc.x += b.x; acc.y += b.y; acc.z += b.z; acc.w += b.w;
    }
    *((float4*)out + (size_t)node * 32 + lane) = acc;
}

// ---------------- launch -----------------------------------------------------
extern "C" void kernel_launch(void* const* d_in, const int* in_sizes, int n_in,
                              void* d_out, int out_size)
{
    const float* emb = (const float*)d_in[0];   // [N, D]
    const float* W1  = (const float*)d_in[1];   // [D, H]
    const float* b1  = (const float*)d_in[2];   // [H]
    const float* W2  = (const float*)d_in[3];   // [H, D]
    const float* b2  = (const float*)d_in[4];   // [D]
    const void*  eix = d_in[5];                 // [2, E] int64 or int32
    float* out = (float*)d_out;                 // [N, D]

    const int D = in_sizes[4];          // 128
    const int H = in_sizes[2];          // 256
    const int N = in_sizes[0] / D;      // 100000
    const int E = in_sizes[5] / 2;      // 1600000
    const int NB = (N + 1023) / 1024;   // 98 scan blocks (co-resident)

    float *p_aggemb, *p_x, *p_xw2;
    int* p_cnt;
    cudaGetSymbolAddress((void**)&p_aggemb, g_aggemb);
    cudaGetSymbolAddress((void**)&p_x,      g_x);
    cudaGetSymbolAddress((void**)&p_xw2,    g_xw2);
    cudaGetSymbolAddress((void**)&p_cnt,    g_cnt);

    // ---- graph prep: memset + 3 kernels ----
    cudaMemsetAsync(p_cnt, 0, (size_t)N * sizeof(int));
    count_kernel<<<(E + 255) / 256, 256>>>((const unsigned int*)eix, E);
    scan_fused_kernel<<<NB, 1024>>>(N);
    csr_fill_kernel<<<(E + 255) / 256, 256>>>((const unsigned int*)eix, E);

    // ---- layer 1: aggemb = agg(emb); x = relu(aggemb @ W1 + b1) ----
    agg128<false><<<(N + 7) / 8, 256>>>(emb, nullptr, p_aggemb, N);
    {
        dim3 grid(H / 128, (N + 127) / 128);
        gemm_f16<true><<<grid, 256>>>(p_aggemb, W1, b1, p_x, N, H, D);
    }

    // ---- layer 2: xw2 = x @ W2; out = agg(xw2) + b2 ----
    {
        dim3 grid(D / 128, (N + 127) / 128);
        gemm_f16<false><<<grid, 256>>>(p_x, W2, nullptr, p_xw2, N, D, H);
    }
    agg128<true><<<(N + 7) / 8, 256>>>(p_xw2, b2, out, N);
}

// round 16
// speedup vs baseline: 1.3513x; 1.1465x over previous
#include <cuda_runtime.h>
#include <cuda_bf16.h>
#include <cuda_fp16.h>
#include <cstdint>

// Problem constants (GCNEncoder_55052890800619)
#define NN 100000
#define DD 128
#define HH 256
#define EE 1600000

// ---------------- scratch (device globals; no allocations allowed) ----------
__device__ int   g_cnt[NN];
__device__ int   g_rowptr[NN];
__device__ int   g_cursor[NN];
__device__ float g_dinv[NN];
__device__ int   g_chain[128];               // scan aggregates (value+1; 0 = unpublished)
__device__ __align__(16) int2     g_csr[EE];                      // 12.8 MB
__device__ __align__(16) float    g_aggemb[(size_t)NN * DD];      // 51.2 MB  agg(emb)
__device__ __align__(16) uint32_t g_xh[(size_t)NN * (HH / 2)];    // 51.2 MB  x as half2
__device__ __align__(16) float    g_xw2[(size_t)NN * DD];         // 51.2 MB

// ---------------- per-block edge dtype detection -----------------------------
__device__ __forceinline__ int block_detect_is64(const unsigned int* __restrict__ p,
                                                 int* s_is64) {
    if (threadIdx.x < 32) {
        int any = 0;
        #pragma unroll
        for (int q = 0; q < 2; q++) {
            long long j = (long long)(threadIdx.x * 2 + q) * 24999 + 7;  // < 1.6M
            any |= (p[2 * j + 1] != 0u);
        }
        any = __any_sync(0xffffffffu, any);
        if (threadIdx.x == 0) *s_is64 = any ? 0 : 1;
    }
    __syncthreads();
    return *s_is64;
}

__device__ __forceinline__ int2 load_edge(const void* eptr, int E, int e, int is64) {
    int2 r;
    if (is64) {
        const long long* q = (const long long*)eptr;
        r.x = (int)q[e];
        r.y = (int)q[(size_t)E + e];
    } else {
        const int* q = (const int*)eptr;
        r.x = q[e];
        r.y = q[(size_t)E + e];
    }
    return r;
}

// ---------------- prep kernels (3 launches) ----------------------------------
__global__ void count_kernel(const unsigned int* __restrict__ eptr, int E) {
    __shared__ int s_is64;
    int is64 = block_detect_is64(eptr, &s_is64);
    if (blockIdx.x == 0 && threadIdx.x < 128) g_chain[threadIdx.x] = 0;
    int e = blockIdx.x * blockDim.x + threadIdx.x;
    if (e >= E) return;
    int d;
    if (is64) d = (int)(((const long long*)eptr)[(size_t)E + e]);
    else      d = ((const int*)eptr)[(size_t)E + e];
    atomicAdd(&g_cnt[d], 1);
}

__global__ void scan_fused_kernel(int n) {
    __shared__ int sh[1024];
    __shared__ int agg[128];
    __shared__ int s_prefix;
    const int b   = blockIdx.x;
    const int tid = threadIdx.x;
    const int gid = b * 1024 + tid;

    int v = (gid < n) ? g_cnt[gid] : 0;
    if (gid < n) g_dinv[gid] = rsqrtf((float)v + 1.0f);
    sh[tid] = v;
    __syncthreads();
    for (int off = 1; off < 1024; off <<= 1) {
        int t = (tid >= (unsigned)off) ? sh[tid - off] : 0;
        __syncthreads();
        sh[tid] += t;
        __syncthreads();
    }
    if (tid == 0) atomicExch(&g_chain[b], sh[1023] + 1);
    if (tid < 128) agg[tid] = 0;
    if (tid < b) {
        int p;
        do { p = atomicAdd(&g_chain[tid], 0); } while (p == 0);
        agg[tid] = p - 1;
    }
    __syncthreads();
    if (tid == 0) {
        int s = 0;
        #pragma unroll 4
        for (int i = 0; i < b; i++) s += agg[i];
        s_prefix = s;
    }
    __syncthreads();
    if (gid < n) {
        int r = s_prefix + sh[tid] - v;
        g_rowptr[gid] = r;
        g_cursor[gid] = r;
    }
}

__global__ void csr_fill_kernel(const unsigned int* __restrict__ eptr, int E) {
    __shared__ int s_is64;
    int is64 = block_detect_is64(eptr, &s_is64);
    int e = blockIdx.x * blockDim.x + threadIdx.x;
    if (e >= E) return;
    int2 sd = load_edge(eptr, E, e, is64);
    int pos = atomicAdd(&g_cursor[sd.y], 1);
    float w = g_dinv[sd.x] * g_dinv[sd.y];
    g_csr[pos] = make_int2(sd.x, __float_as_int(w));
}

// ---------------- fp16 helpers ----------------------------------------------
__device__ __forceinline__ uint32_t pack_f16(float x0, float x1) {
    uint32_t h;
    asm("cvt.rn.f16x2.f32 %0, %1, %2;" : "=r"(h) : "f"(x1), "f"(x0));
    return h;   // low half = x0, high half = x1
}

__device__ __forceinline__ void mma16f(float* c, const uint32_t* a, const uint32_t* b) {
    asm volatile(
        "mma.sync.aligned.m16n8k16.row.col.f32.f16.f16.f32 "
        "{%0,%1,%2,%3}, {%4,%5,%6,%7}, {%8,%9}, {%0,%1,%2,%3};"
        : "+f"(c[0]), "+f"(c[1]), "+f"(c[2]), "+f"(c[3])
        : "r"(a[0]), "r"(a[1]), "r"(a[2]), "r"(a[3]), "r"(b[0]), "r"(b[1]));
}

// kpair (0..7) -> smem column (pairs (t, t+4) adjacent -> one LDS.64/frag)
__device__ __forceinline__ int colmap(int kp) {
    return ((kp & 3) << 1) | ((kp >> 2) & 1);
}

// ---------------- GEMM: fp16 1-term, pipelined -------------------------------
// Block 128x128, BK=16, 256 threads = 8 warps, warp tile 64x32, 2 CTAs/SM.
// A_HALF: A given as half2 words (row-major, natural k order).
// OUT_HALF: write C as half2 words; else fp32.
#define GSTR 10

template <bool A_HALF, bool RELU_BIAS, bool OUT_HALF>
__global__ void __launch_bounds__(256, 2)
gemm_f16(const void* __restrict__ Aptr, const float* __restrict__ B,
         const float* __restrict__ bias, void* __restrict__ Cptr,
         int M, int N, int K)
{
    __shared__ uint32_t Ahs[2][128][GSTR];
    __shared__ uint32_t Bhs[2][128][GSTR];

    const int tid  = threadIdx.x;
    const int wid  = tid >> 5;
    const int lane = tid & 31;
    const int g    = lane >> 2;
    const int t    = lane & 3;
    const int brow = blockIdx.y * 128;
    const int bcol = blockIdx.x * 128;
    const int wm   = (wid >> 2) * 64;   // 0 or 64
    const int wn   = (wid & 3) * 32;    // 0,32,64,96

    // fp32-A loader indices
    const int am0  = tid >> 2;          // A row for q=0 (0..63)
    const int akq0 = tid & 3;           // A float4-k
    // half-A loader indices
    const int ahm  = tid >> 1;          // 0..127
    const int apart = tid & 1;          // kpair group (0: kp0..3, 1: kp4..7)
    // B loader indices
    const int bkp  = tid >> 5;          // B kpair 0..7
    const int bn4  = tid & 31;          // B float4-n

    const int ngrp = K >> 4;

    float acc[4][4][4];
    #pragma unroll
    for (int mt = 0; mt < 4; mt++)
        #pragma unroll
        for (int nt = 0; nt < 4; nt++)
            #pragma unroll
            for (int i = 0; i < 4; i++) acc[mt][nt][i] = 0.0f;

    float4 va0, va1, vb0, vb1;
    uint4  wa;

    auto fetch = [&](int grp) {
        int k0 = grp * 16;
        if (A_HALF) {
            const uint32_t* Ah = (const uint32_t*)Aptr;
            wa = make_uint4(0, 0, 0, 0);
            if (brow + ahm < M)
                wa = *(const uint4*)(Ah + (size_t)(brow + ahm) * (K / 2) + grp * 8 + apart * 4);
        } else {
            const float* A = (const float*)Aptr;
            int r0 = brow + am0;
            int r1 = brow + am0 + 64;
            va0 = make_float4(0.f, 0.f, 0.f, 0.f);
            va1 = make_float4(0.f, 0.f, 0.f, 0.f);
            if (r0 < M) va0 = *(const float4*)(A + (size_t)r0 * K + k0 + akq0 * 4);
            if (r1 < M) va1 = *(const float4*)(A + (size_t)r1 * K + k0 + akq0 * 4);
        }
        const float* br = B + (size_t)(k0 + 2 * bkp) * N + bcol + bn4 * 4;
        vb0 = *(const float4*)br;
        vb1 = *(const float4*)(br + N);
    };
    auto stage = [&](int buf) {
        if (A_HALF) {
            Ahs[buf][ahm][colmap(apart * 4 + 0)] = wa.x;
            Ahs[buf][ahm][colmap(apart * 4 + 1)] = wa.y;
            Ahs[buf][ahm][colmap(apart * 4 + 2)] = wa.z;
            Ahs[buf][ahm][colmap(apart * 4 + 3)] = wa.w;
        } else {
            int c0 = colmap(2 * akq0), c1 = colmap(2 * akq0 + 1);
            Ahs[buf][am0][c0]      = pack_f16(va0.x, va0.y);
            Ahs[buf][am0][c1]      = pack_f16(va0.z, va0.w);
            Ahs[buf][am0 + 64][c0] = pack_f16(va1.x, va1.y);
            Ahs[buf][am0 + 64][c1] = pack_f16(va1.z, va1.w);
        }
        int cb = colmap(bkp);
        Bhs[buf][bn4 * 4 + 0][cb] = pack_f16(vb0.x, vb1.x);
        Bhs[buf][bn4 * 4 + 1][cb] = pack_f16(vb0.y, vb1.y);
        Bhs[buf][bn4 * 4 + 2][cb] = pack_f16(vb0.z, vb1.z);
        Bhs[buf][bn4 * 4 + 3][cb] = pack_f16(vb0.w, vb1.w);
    };

    fetch(0);
    stage(0);
    __syncthreads();

    for (int grp = 0; grp < ngrp; grp++) {
        int cur = grp & 1;
        if (grp + 1 < ngrp) fetch(grp + 1);

        {
            const int cb = 2 * t;
            uint32_t ah[4][4];
            #pragma unroll
            for (int mt = 0; mt < 4; mt++) {
                int r = wm + mt * 16;
                uint2 p0 = *(const uint2*)&Ahs[cur][r + g    ][cb];
                uint2 p1 = *(const uint2*)&Ahs[cur][r + g + 8][cb];
                ah[mt][0] = p0.x; ah[mt][2] = p0.y;
                ah[mt][1] = p1.x; ah[mt][3] = p1.y;
            }
            #pragma unroll
            for (int nt = 0; nt < 4; nt++) {
                uint2 bh2 = *(const uint2*)&Bhs[cur][wn + nt * 8 + g][cb];
                uint32_t bh[2] = {bh2.x, bh2.y};
                #pragma unroll
                for (int mt = 0; mt < 4; mt++)
                    mma16f(acc[mt][nt], ah[mt], bh);
            }
        }

        if (grp + 1 < ngrp) stage(cur ^ 1);
        __syncthreads();
    }

    #pragma unroll
    for (int nt = 0; nt < 4; nt++) {
        int col = bcol + wn + nt * 8 + 2 * t;
        float b0 = 0.f, b1 = 0.f;
        if (RELU_BIAS) { b0 = bias[col]; b1 = bias[col + 1]; }
        #pragma unroll
        for (int mt = 0; mt < 4; mt++) {
            int r0 = brow + wm + mt * 16 + g;
            float2 v0 = make_float2(acc[mt][nt][0] + b0, acc[mt][nt][1] + b1);
            float2 v1 = make_float2(acc[mt][nt][2] + b0, acc[mt][nt][3] + b1);
            if (RELU_BIAS) {
                v0.x = fmaxf(v0.x, 0.f); v0.y = fmaxf(v0.y, 0.f);
                v1.x = fmaxf(v1.x, 0.f); v1.y = fmaxf(v1.y, 0.f);
            }
            if (OUT_HALF) {
                uint32_t* Ch = (uint32_t*)Cptr;
                if (r0 < M)
                    Ch[(size_t)r0 * (N / 2) + (col >> 1)] = pack_f16(v0.x, v0.y);
                if (r0 + 8 < M)
                    Ch[(size_t)(r0 + 8) * (N / 2) + (col >> 1)] = pack_f16(v1.x, v1.y);
            } else {
                float* Cf = (float*)Cptr;
                if (r0 < M)     *(float2*)(Cf + (size_t)r0 * N + col) = v0;
                if (r0 + 8 < M) *(float2*)(Cf + (size_t)(r0 + 8) * N + col) = v1;
            }
        }
    }
}

// ---------------- aggregation (128 cols): warp per node, MLP=8 --------------
template <bool ADD_BIAS>
__global__ void __launch_bounds__(256)
agg128(const float* __restrict__ xw, const float* __restrict__ bias,
       float* __restrict__ out, int n)
{
    int node = (blockIdx.x * 256 + threadIdx.x) >> 5;
    int lane = threadIdx.x & 31;
    if (node >= n) return;

    float dsq = g_dinv[node];
    dsq *= dsq;
    const float4* base = (const float4*)xw;
    float4 tv = base[(size_t)node * 32 + lane];
    float4 acc = make_float4(tv.x * dsq, tv.y * dsq, tv.z * dsq, tv.w * dsq);

    int j   = g_rowptr[node];
    int end = j + g_cnt[node];

    for (; j + 8 <= end; j += 8) {
        int2 e[8];
        #pragma unroll
        for (int q = 0; q < 8; q++) e[q] = g_csr[j + q];
        float4 p[8];
        #pragma unroll
        for (int q = 0; q < 8; q++) p[q] = base[(size_t)e[q].x * 32 + lane];
        #pragma unroll
        for (int q = 0; q < 8; q++) {
            float w = __int_as_float(e[q].y);
            acc.x = fmaf(p[q].x, w, acc.x); acc.y = fmaf(p[q].y, w, acc.y);
            acc.z = fmaf(p[q].z, w, acc.z); acc.w = fmaf(p[q].w, w, acc.w);
        }
    }
    if (j + 4 <= end) {
        int2 e[4];
        #pragma unroll
        for (int q = 0; q < 4; q++) e[q] = g_csr[j + q];
        float4 p[4];
        #pragma unroll
        for (int q = 0; q < 4; q++) p[q] = base[(size_t)e[q].x * 32 + lane];
        #pragma unroll
        for (int q = 0; q < 4; q++) {
            float w = __int_as_float(e[q].y);
            acc.x = fmaf(p[q].x, w, acc.x); acc.y = fmaf(p[q].y, w, acc.y);
            acc.z = fmaf(p[q].z, w, acc.z); acc.w = fmaf(p[q].w, w, acc.w);
        }
        j += 4;
    }
    for (; j < end; j++) {
        int2 e = g_csr[j];
        float w = __int_as_float(e.y);
        float4 p = base[(size_t)e.x * 32 + lane];
        acc.x = fmaf(p.x, w, acc.x); acc.y = fmaf(p.y, w, acc.y);
        acc.z = fmaf(p.z, w, acc.z); acc.w = fmaf(p.w, w, acc.w);
    }

    if (ADD_BIAS) {
        float4 b = *((const float4*)bias + lane);
        acc.x += b.x; acc.y += b.y; acc.z += b.z; acc.w += b.w;
    }
    *((float4*)out + (size_t)node * 32 + lane) = acc;
}

// ---------------- launch -----------------------------------------------------
extern "C" void kernel_launch(void* const* d_in, const int* in_sizes, int n_in,
                              void* d_out, int out_size)
{
    const float* emb = (const float*)d_in[0];   // [N, D]
    const float* W1  = (const float*)d_in[1];   // [D, H]
    const float* b1  = (const float*)d_in[2];   // [H]
    const float* W2  = (const float*)d_in[3];   // [H, D]
    const float* b2  = (const float*)d_in[4];   // [D]
    const void*  eix = d_in[5];                 // [2, E] int64 or int32
    float* out = (float*)d_out;                 // [N, D]

    const int D = in_sizes[4];          // 128
    const int H = in_sizes[2];          // 256
    const int N = in_sizes[0] / D;      // 100000
    const int E = in_sizes[5] / 2;      // 1600000
    const int NB = (N + 1023) / 1024;   // 98 scan blocks (co-resident)

    float *p_aggemb, *p_xw2;
    uint32_t* p_xh;
    int* p_cnt;
    cudaGetSymbolAddress((void**)&p_aggemb, g_aggemb);
    cudaGetSymbolAddress((void**)&p_xh,     g_xh);
    cudaGetSymbolAddress((void**)&p_xw2,    g_xw2);
    cudaGetSymbolAddress((void**)&p_cnt,    g_cnt);

    // ---- graph prep: memset + 3 kernels ----
    cudaMemsetAsync(p_cnt, 0, (size_t)N * sizeof(int));
    count_kernel<<<(E + 255) / 256, 256>>>((const unsigned int*)eix, E);
    scan_fused_kernel<<<NB, 1024>>>(N);
    csr_fill_kernel<<<(E + 255) / 256, 256>>>((const unsigned int*)eix, E);

    // ---- layer 1: aggemb = agg(emb); xh = half(relu(aggemb @ W1 + b1)) ----
    agg128<false><<<(N + 7) / 8, 256>>>(emb, nullptr, p_aggemb, N);
    {
        dim3 grid(H / 128, (N + 127) / 128);
        gemm_f16<false, true, true><<<grid, 256>>>(p_aggemb, W1, b1, p_xh, N, H, D);
    }

    // ---- layer 2: xw2 = xh @ W2; out = agg(xw2) + b2 ----
    {
        dim3 grid(D / 128, (N + 127) / 128);
        gemm_f16<true, false, false><<<grid, 256>>>(p_xh, W2, nullptr, p_xw2, N, D, H);
    }
    agg128<true><<<(N + 7) / 8, 256>>>(p_xw2, b2, out, N);
}

// round 17
// speedup vs baseline: 1.4961x; 1.1071x over previous
#include <cuda_runtime.h>
#include <cuda_bf16.h>
#include <cuda_fp16.h>
#include <cstdint>

// Problem constants (GCNEncoder_55052890800619)
#define NN 100000
#define DD 128
#define HH 256
#define EE 1600000

// ---------------- scratch (device globals; no allocations allowed) ----------
__device__ int   g_cnt[NN];
__device__ int   g_rowptr[NN];
__device__ int   g_cursor[NN];
__device__ float g_dinv[NN];
__device__ int   g_chain[128];               // scan aggregates (value+1; 0 = unpublished)
__device__ __align__(16) int2     g_csr[EE];                        // 12.8 MB
__device__ __align__(16) uint32_t g_embh  [(size_t)NN * (DD / 2)];  // 25.6 MB emb as half2
__device__ __align__(16) uint32_t g_aggembh[(size_t)NN * (DD / 2)]; // 25.6 MB agg(emb) half2
__device__ __align__(16) uint32_t g_xh [(size_t)NN * (HH / 2)];     // 51.2 MB x as half2
__device__ __align__(16) uint32_t g_xw2h[(size_t)NN * (DD / 2)];    // 25.6 MB xw2 as half2

// ---------------- per-block edge dtype detection -----------------------------
__device__ __forceinline__ int block_detect_is64(const unsigned int* __restrict__ p,
                                                 int* s_is64) {
    if (threadIdx.x < 32) {
        int any = 0;
        #pragma unroll
        for (int q = 0; q < 2; q++) {
            long long j = (long long)(threadIdx.x * 2 + q) * 24999 + 7;  // < 1.6M
            any |= (p[2 * j + 1] != 0u);
        }
        any = __any_sync(0xffffffffu, any);
        if (threadIdx.x == 0) *s_is64 = any ? 0 : 1;
    }
    __syncthreads();
    return *s_is64;
}

__device__ __forceinline__ int2 load_edge(const void* eptr, int E, int e, int is64) {
    int2 r;
    if (is64) {
        const long long* q = (const long long*)eptr;
        r.x = (int)q[e];
        r.y = (int)q[(size_t)E + e];
    } else {
        const int* q = (const int*)eptr;
        r.x = q[e];
        r.y = q[(size_t)E + e];
    }
    return r;
}

// ---------------- fp16 helpers ----------------------------------------------
__device__ __forceinline__ uint32_t pack_f16(float x0, float x1) {
    uint32_t h;
    asm("cvt.rn.f16x2.f32 %0, %1, %2;" : "=r"(h) : "f"(x1), "f"(x0));
    return h;   // low half = x0, high half = x1
}

__device__ __forceinline__ float2 unpack_f16(uint32_t w) {
    __half2 h = *reinterpret_cast<__half2*>(&w);
    return __half22float2(h);
}

// ---------------- prep kernels ----------------------------------------------
__global__ void count_kernel(const unsigned int* __restrict__ eptr, int E) {
    __shared__ int s_is64;
    int is64 = block_detect_is64(eptr, &s_is64);
    if (blockIdx.x == 0 && threadIdx.x < 128) g_chain[threadIdx.x] = 0;
    int e = blockIdx.x * blockDim.x + threadIdx.x;
    if (e >= E) return;
    int d;
    if (is64) d = (int)(((const long long*)eptr)[(size_t)E + e]);
    else      d = ((const int*)eptr)[(size_t)E + e];
    atomicAdd(&g_cnt[d], 1);
}

__global__ void scan_fused_kernel(int n) {
    __shared__ int sh[1024];
    __shared__ int agg[128];
    __shared__ int s_prefix;
    const int b   = blockIdx.x;
    const int tid = threadIdx.x;
    const int gid = b * 1024 + tid;

    int v = (gid < n) ? g_cnt[gid] : 0;
    if (gid < n) g_dinv[gid] = rsqrtf((float)v + 1.0f);
    sh[tid] = v;
    __syncthreads();
    for (int off = 1; off < 1024; off <<= 1) {
        int t = (tid >= (unsigned)off) ? sh[tid - off] : 0;
        __syncthreads();
        sh[tid] += t;
        __syncthreads();
    }
    if (tid == 0) atomicExch(&g_chain[b], sh[1023] + 1);
    if (tid < 128) agg[tid] = 0;
    if (tid < b) {
        int p;
        do { p = atomicAdd(&g_chain[tid], 0); } while (p == 0);
        agg[tid] = p - 1;
    }
    __syncthreads();
    if (tid == 0) {
        int s = 0;
        #pragma unroll 4
        for (int i = 0; i < b; i++) s += agg[i];
        s_prefix = s;
    }
    __syncthreads();
    if (gid < n) {
        int r = s_prefix + sh[tid] - v;
        g_rowptr[gid] = r;
        g_cursor[gid] = r;
    }
}

__global__ void csr_fill_kernel(const unsigned int* __restrict__ eptr, int E) {
    __shared__ int s_is64;
    int is64 = block_detect_is64(eptr, &s_is64);
    int e = blockIdx.x * blockDim.x + threadIdx.x;
    if (e >= E) return;
    int2 sd = load_edge(eptr, E, e, is64);
    int pos = atomicAdd(&g_cursor[sd.y], 1);
    float w = g_dinv[sd.x] * g_dinv[sd.y];
    g_csr[pos] = make_int2(sd.x, __float_as_int(w));
}

// fp32 -> half2 streaming convert
__global__ void f2h_kernel(const float2* __restrict__ in,
                           uint32_t* __restrict__ out, int nw) {
    int i = blockIdx.x * blockDim.x + threadIdx.x;
    if (i >= nw) return;
    float2 v = in[i];
    out[i] = pack_f16(v.x, v.y);
}

__device__ __forceinline__ void mma16f(float* c, const uint32_t* a, const uint32_t* b) {
    asm volatile(
        "mma.sync.aligned.m16n8k16.row.col.f32.f16.f16.f32 "
        "{%0,%1,%2,%3}, {%4,%5,%6,%7}, {%8,%9}, {%0,%1,%2,%3};"
        : "+f"(c[0]), "+f"(c[1]), "+f"(c[2]), "+f"(c[3])
        : "r"(a[0]), "r"(a[1]), "r"(a[2]), "r"(a[3]), "r"(b[0]), "r"(b[1]));
}

// kpair (0..7) -> smem column (pairs (t, t+4) adjacent -> one LDS.64/frag)
__device__ __forceinline__ int colmap(int kp) {
    return ((kp & 3) << 1) | ((kp >> 2) & 1);
}

// ---------------- GEMM: fp16 1-term, pipelined, A half2 ----------------------
// Block 128x128, BK=16, 256 threads = 8 warps, warp tile 64x32, 2 CTAs/SM.
#define GSTR 10

template <bool RELU_BIAS>
__global__ void __launch_bounds__(256, 2)
gemm_f16(const uint32_t* __restrict__ Ah, const float* __restrict__ B,
         const float* __restrict__ bias, uint32_t* __restrict__ Ch,
         int M, int N, int K)
{
    __shared__ uint32_t Ahs[2][128][GSTR];
    __shared__ uint32_t Bhs[2][128][GSTR];

    const int tid  = threadIdx.x;
    const int wid  = tid >> 5;
    const int lane = tid & 31;
    const int g    = lane >> 2;
    const int t    = lane & 3;
    const int brow = blockIdx.y * 128;
    const int bcol = blockIdx.x * 128;
    const int wm   = (wid >> 2) * 64;   // 0 or 64
    const int wn   = (wid & 3) * 32;    // 0,32,64,96

    const int ahm   = tid >> 1;         // A row 0..127
    const int apart = tid & 1;          // kpair group (0: kp0..3, 1: kp4..7)
    const int bkp   = tid >> 5;         // B kpair 0..7
    const int bn4   = tid & 31;         // B float4-n

    const int ngrp = K >> 4;

    float acc[4][4][4];
    #pragma unroll
    for (int mt = 0; mt < 4; mt++)
        #pragma unroll
        for (int nt = 0; nt < 4; nt++)
            #pragma unroll
            for (int i = 0; i < 4; i++) acc[mt][nt][i] = 0.0f;

    float4 vb0, vb1;
    uint4  wa;

    auto fetch = [&](int grp) {
        int k0 = grp * 16;
        wa = make_uint4(0, 0, 0, 0);
        if (brow + ahm < M)
            wa = *(const uint4*)(Ah + (size_t)(brow + ahm) * (K / 2) + grp * 8 + apart * 4);
        const float* br = B + (size_t)(k0 + 2 * bkp) * N + bcol + bn4 * 4;
        vb0 = *(const float4*)br;
        vb1 = *(const float4*)(br + N);
    };
    auto stage = [&](int buf) {
        Ahs[buf][ahm][colmap(apart * 4 + 0)] = wa.x;
        Ahs[buf][ahm][colmap(apart * 4 + 1)] = wa.y;
        Ahs[buf][ahm][colmap(apart * 4 + 2)] = wa.z;
        Ahs[buf][ahm][colmap(apart * 4 + 3)] = wa.w;
        int cb = colmap(bkp);
        Bhs[buf][bn4 * 4 + 0][cb] = pack_f16(vb0.x, vb1.x);
        Bhs[buf][bn4 * 4 + 1][cb] = pack_f16(vb0.y, vb1.y);
        Bhs[buf][bn4 * 4 + 2][cb] = pack_f16(vb0.z, vb1.z);
        Bhs[buf][bn4 * 4 + 3][cb] = pack_f16(vb0.w, vb1.w);
    };

    fetch(0);
    stage(0);
    __syncthreads();

    for (int grp = 0; grp < ngrp; grp++) {
        int cur = grp & 1;
        if (grp + 1 < ngrp) fetch(grp + 1);

        {
            const int cb = 2 * t;
            uint32_t ah[4][4];
            #pragma unroll
            for (int mt = 0; mt < 4; mt++) {
                int r = wm + mt * 16;
                uint2 p0 = *(const uint2*)&Ahs[cur][r + g    ][cb];
                uint2 p1 = *(const uint2*)&Ahs[cur][r + g + 8][cb];
                ah[mt][0] = p0.x; ah[mt][2] = p0.y;
                ah[mt][1] = p1.x; ah[mt][3] = p1.y;
            }
            #pragma unroll
            for (int nt = 0; nt < 4; nt++) {
                uint2 bh2 = *(const uint2*)&Bhs[cur][wn + nt * 8 + g][cb];
                uint32_t bh[2] = {bh2.x, bh2.y};
                #pragma unroll
                for (int mt = 0; mt < 4; mt++)
                    mma16f(acc[mt][nt], ah[mt], bh);
            }
        }

        if (grp + 1 < ngrp) stage(cur ^ 1);
        __syncthreads();
    }

    // epilogue: optional bias+relu, pack to half2
    #pragma unroll
    for (int nt = 0; nt < 4; nt++) {
        int col = bcol + wn + nt * 8 + 2 * t;
        float b0 = 0.f, b1 = 0.f;
        if (RELU_BIAS) { b0 = bias[col]; b1 = bias[col + 1]; }
        #pragma unroll
        for (int mt = 0; mt < 4; mt++) {
            int r0 = brow + wm + mt * 16 + g;
            float2 v0 = make_float2(acc[mt][nt][0] + b0, acc[mt][nt][1] + b1);
            float2 v1 = make_float2(acc[mt][nt][2] + b0, acc[mt][nt][3] + b1);
            if (RELU_BIAS) {
                v0.x = fmaxf(v0.x, 0.f); v0.y = fmaxf(v0.y, 0.f);
                v1.x = fmaxf(v1.x, 0.f); v1.y = fmaxf(v1.y, 0.f);
            }
            if (r0 < M)
                Ch[(size_t)r0 * (N / 2) + (col >> 1)] = pack_f16(v0.x, v0.y);
            if (r0 + 8 < M)
                Ch[(size_t)(r0 + 8) * (N / 2) + (col >> 1)] = pack_f16(v1.x, v1.y);
        }
    }
}

// ---------------- aggregation (128 cols, half2 source): warp/node, MLP=8 -----
// Gathers uint2 (4 halfs) per lane (256 B/row), accumulates fp32.
// OUT_HALF: emit half2; else fp32 (+bias).
template <bool ADD_BIAS, bool OUT_HALF>
__global__ void __launch_bounds__(256)
agg128h(const uint2* __restrict__ xw, const float* __restrict__ bias,
        void* __restrict__ out, int n)
{
    int node = (blockIdx.x * 256 + threadIdx.x) >> 5;
    int lane = threadIdx.x & 31;
    if (node >= n) return;

    float dsq = g_dinv[node];
    dsq *= dsq;
    uint2 tw = xw[(size_t)node * 32 + lane];
    float2 t0 = unpack_f16(tw.x), t1 = unpack_f16(tw.y);
    float4 acc = make_float4(t0.x * dsq, t0.y * dsq, t1.x * dsq, t1.y * dsq);

    int j   = g_rowptr[node];
    int end = j + g_cnt[node];

    for (; j + 8 <= end; j += 8) {
        int2 e[8];
        #pragma unroll
        for (int q = 0; q < 8; q++) e[q] = g_csr[j + q];
        uint2 p[8];
        #pragma unroll
        for (int q = 0; q < 8; q++) p[q] = xw[(size_t)e[q].x * 32 + lane];
        #pragma unroll
        for (int q = 0; q < 8; q++) {
            float w = __int_as_float(e[q].y);
            float2 a = unpack_f16(p[q].x), b = unpack_f16(p[q].y);
            acc.x = fmaf(a.x, w, acc.x); acc.y = fmaf(a.y, w, acc.y);
            acc.z = fmaf(b.x, w, acc.z); acc.w = fmaf(b.y, w, acc.w);
        }
    }
    if (j + 4 <= end) {
        int2 e[4];
        #pragma unroll
        for (int q = 0; q < 4; q++) e[q] = g_csr[j + q];
        uint2 p[4];
        #pragma unroll
        for (int q = 0; q < 4; q++) p[q] = xw[(size_t)e[q].x * 32 + lane];
        #pragma unroll
        for (int q = 0; q < 4; q++) {
            float w = __int_as_float(e[q].y);
            float2 a = unpack_f16(p[q].x), b = unpack_f16(p[q].y);
            acc.x = fmaf(a.x, w, acc.x); acc.y = fmaf(a.y, w, acc.y);
            acc.z = fmaf(b.x, w, acc.z); acc.w = fmaf(b.y, w, acc.w);
        }
        j += 4;
    }
    for (; j < end; j++) {
        int2 e = g_csr[j];
        float w = __int_as_float(e.y);
        uint2 p = xw[(size_t)e.x * 32 + lane];
        float2 a = unpack_f16(p.x), b = unpack_f16(p.y);
        acc.x = fmaf(a.x, w, acc.x); acc.y = fmaf(a.y, w, acc.y);
        acc.z = fmaf(b.x, w, acc.z); acc.w = fmaf(b.y, w, acc.w);
    }

    if (ADD_BIAS) {
        float4 b = *((const float4*)bias + lane);
        acc.x += b.x; acc.y += b.y; acc.z += b.z; acc.w += b.w;
    }
    if (OUT_HALF) {
        uint2 o = make_uint2(pack_f16(acc.x, acc.y), pack_f16(acc.z, acc.w));
        ((uint2*)out)[(size_t)node * 32 + lane] = o;
    } else {
        ((float4*)out)[(size_t)node * 32 + lane] = acc;
    }
}

// ---------------- launch -----------------------------------------------------
extern "C" void kernel_launch(void* const* d_in, const int* in_sizes, int n_in,
                              void* d_out, int out_size)
{
    const float* emb = (const float*)d_in[0];   // [N, D]
    const float* W1  = (const float*)d_in[1];   // [D, H]
    const float* b1  = (const float*)d_in[2];   // [H]
    const float* W2  = (const float*)d_in[3];   // [H, D]
    const float* b2  = (const float*)d_in[4];   // [D]
    const void*  eix = d_in[5];                 // [2, E] int64 or int32
    float* out = (float*)d_out;                 // [N, D]

    const int D = in_sizes[4];          // 128
    const int H = in_sizes[2];          // 256
    const int N = in_sizes[0] / D;      // 100000
    const int E = in_sizes[5] / 2;      // 1600000
    const int NB = (N + 1023) / 1024;   // 98 scan blocks (co-resident)

    uint32_t *p_embh, *p_aggembh, *p_xh, *p_xw2h;
    int* p_cnt;
    cudaGetSymbolAddress((void**)&p_embh,    g_embh);
    cudaGetSymbolAddress((void**)&p_aggembh, g_aggembh);
    cudaGetSymbolAddress((void**)&p_xh,      g_xh);
    cudaGetSymbolAddress((void**)&p_xw2h,    g_xw2h);
    cudaGetSymbolAddress((void**)&p_cnt,     g_cnt);

    // ---- graph prep: memset + 3 kernels, plus emb->half convert ----
    cudaMemsetAsync(p_cnt, 0, (size_t)N * sizeof(int));
    count_kernel<<<(E + 255) / 256, 256>>>((const unsigned int*)eix, E);
    f2h_kernel<<<(N * D / 2 + 255) / 256, 256>>>((const float2*)emb, p_embh, N * D / 2);
    scan_fused_kernel<<<NB, 1024>>>(N);
    csr_fill_kernel<<<(E + 255) / 256, 256>>>((const unsigned int*)eix, E);

    // ---- layer 1: aggembh = agg(embh); xh = half(relu(aggembh @ W1 + b1)) ----
    agg128h<false, true><<<(N + 7) / 8, 256>>>((const uint2*)p_embh, nullptr, p_aggembh, N);
    {
        dim3 grid(H / 128, (N + 127) / 128);
        gemm_f16<true><<<grid, 256>>>(p_aggembh, W1, b1, p_xh, N, H, D);
    }

    // ---- layer 2: xw2h = xh @ W2; out = agg(xw2h) + b2 ----
    {
        dim3 grid(D / 128, (N + 127) / 128);
        gemm_f16<false><<<grid, 256>>>(p_xh, W2, nullptr, p_xw2h, N, D, H);
    }
    agg128h<true, false><<<(N + 7) / 8, 256>>>((const uint2*)p_xw2h, b2, out, N);
}